// round 14
// baseline (speedup 1.0000x reference)
#include <cuda_runtime.h>
#include <cuda_bf16.h>
#include <math.h>
#include <stdint.h>

#define NN 9216
#define DD 1024
#define NB 72          // NN / 128 tile blocks per dim
#define NTILES 2628    // NB*(NB+1)/2 upper-triangular tiles

// -------- device-global accumulators / scratch (no allocations allowed) -----
__device__ float  g_sq[NN];
__device__ float  g_rnorm[NN];
__device__ float  g_agg_sum;
__device__ double g_sim_sum;
__device__ __align__(16) __nv_bfloat16 g_Fbf[(size_t)NN * DD];

// ---------------------------------------------------------------------------
__device__ __forceinline__ uint32_t smem_to_u32(const void* p) {
    uint32_t a;
    asm("{ .reg .u64 t; cvta.to.shared.u64 t, %1; cvt.u32.u64 %0, t; }"
        : "=r"(a) : "l"(p));
    return a;
}

__device__ __forceinline__ void ldsm_x4(uint32_t& r0, uint32_t& r1,
                                        uint32_t& r2, uint32_t& r3, uint32_t addr) {
    asm volatile("ldmatrix.sync.aligned.m8n8.x4.shared.b16 {%0,%1,%2,%3}, [%4];"
                 : "=r"(r0), "=r"(r1), "=r"(r2), "=r"(r3) : "r"(addr));
}

__device__ __forceinline__ void ldsm_x2(uint32_t& r0, uint32_t& r1, uint32_t addr) {
    asm volatile("ldmatrix.sync.aligned.m8n8.x2.shared.b16 {%0,%1}, [%2];"
                 : "=r"(r0), "=r"(r1) : "r"(addr));
}

__device__ __forceinline__ void mma_bf16(float d[4], const uint32_t a[4],
                                         const uint32_t b[2]) {
    asm volatile(
        "mma.sync.aligned.m16n8k16.row.col.f32.bf16.bf16.f32 "
        "{%0,%1,%2,%3}, {%4,%5,%6,%7}, {%8,%9}, {%0,%1,%2,%3};"
        : "+f"(d[0]), "+f"(d[1]), "+f"(d[2]), "+f"(d[3])
        : "r"(a[0]), "r"(a[1]), "r"(a[2]), "r"(a[3]), "r"(b[0]), "r"(b[1]));
}

#define CP_ASYNC16(dst_u32, src_ptr) \
    asm volatile("cp.async.cg.shared.global [%0], [%1], 16;" \
                 :: "r"(dst_u32), "l"(src_ptr))
#define CP_COMMIT() asm volatile("cp.async.commit_group;" ::: "memory")
#define CP_WAIT(n)  asm volatile("cp.async.wait_group %0;" :: "n"(n) : "memory")

// SW64-style swizzle for 64-byte rows: XOR 16B-seg bits [4:5] with (row>>1)&3
// (bits [7:8]). Conflict-free for both ldmatrix phases and k-step XOR-advance.
__device__ __forceinline__ uint32_t swz64(uint32_t off) {
    return off ^ ((off >> 3) & 0x30);
}

// ---------------------------------------------------------------------------
__global__ void init_kernel() {
    g_agg_sum = 0.0f;
    g_sim_sum = 0.0;
}

// one warp per row: squared norm, reciprocal norm, and bf16 conversion
__global__ void prep_kernel(const float* __restrict__ F) {
    int row = blockIdx.x * blockDim.y + threadIdx.y;
    if (row >= NN) return;
    int lane = threadIdx.x;
    const float4* Fr = reinterpret_cast<const float4*>(F + (size_t)row * DD);
    uint2* out = reinterpret_cast<uint2*>(g_Fbf + (size_t)row * DD);
    float s = 0.0f;
#pragma unroll
    for (int w = 0; w < 8; w++) {
        float4 v = Fr[lane + w * 32];
        s += v.x * v.x + v.y * v.y + v.z * v.z + v.w * v.w;
        __nv_bfloat162 lo = __floats2bfloat162_rn(v.x, v.y);
        __nv_bfloat162 hi = __floats2bfloat162_rn(v.z, v.w);
        uint2 u;
        u.x = *reinterpret_cast<uint32_t*>(&lo);
        u.y = *reinterpret_cast<uint32_t*>(&hi);
        out[lane + w * 32] = u;
    }
#pragma unroll
    for (int o = 16; o > 0; o >>= 1) s += __shfl_down_sync(0xffffffffu, s, o);
    if (lane == 0) {
        g_sq[row] = s;
        g_rnorm[row] = rsqrtf(s);
    }
}

// ---------------------------------------------------------------------------
// MLP: 8 rows per block, 128 threads.
__global__ __launch_bounds__(128) void mlp_kernel(
    const float* __restrict__ F, const float* __restrict__ scores,
    const float* __restrict__ W1, const float* __restrict__ b1,
    const float* __restrict__ g1, const float* __restrict__ be1,
    const float* __restrict__ W2, const float* __restrict__ b2,
    const float* __restrict__ g2, const float* __restrict__ be2,
    const float* __restrict__ W3, const float* __restrict__ b3)
{
    __shared__ float xs[8][1028];
    __shared__ float hs[8][128];
    __shared__ float h2s[8][64];

    const int tid = threadIdx.x;
    const int r0  = blockIdx.x * 8;

    for (int idx = tid; idx < 8 * 1024; idx += 128) {
        int r = idx >> 10, k = idx & 1023;
        xs[r][k] = F[(size_t)(r0 + r) * DD + k];
    }
    if (tid < 8) xs[tid][1024] = scores[r0 + tid];
    __syncthreads();

    const float RSQ = rsqrtf(1.0f + 1e-5f);

    {
        const int j = tid;
        float acc[8];
#pragma unroll
        for (int r = 0; r < 8; r++) acc[r] = 0.0f;
        for (int k = 0; k < 1024; k += 4) {
            float w0 = W1[(k + 0) * 128 + j];
            float w1 = W1[(k + 1) * 128 + j];
            float w2 = W1[(k + 2) * 128 + j];
            float w3 = W1[(k + 3) * 128 + j];
#pragma unroll
            for (int r = 0; r < 8; r++) {
                float4 x = *reinterpret_cast<const float4*>(&xs[r][k]);
                acc[r] = fmaf(x.x, w0, acc[r]);
                acc[r] = fmaf(x.y, w1, acc[r]);
                acc[r] = fmaf(x.z, w2, acc[r]);
                acc[r] = fmaf(x.w, w3, acc[r]);
            }
        }
        float wl = W1[1024 * 128 + j];
#pragma unroll
        for (int r = 0; r < 8; r++) acc[r] = fmaf(xs[r][1024], wl, acc[r]);

        const float G = g1[j] * RSQ, B = be1[j], bb = b1[j];
#pragma unroll
        for (int r = 0; r < 8; r++)
            hs[r][j] = fmaxf(fmaf(G, acc[r] + bb, B), 0.0f);
    }
    __syncthreads();

    if (tid < 64) {
        const int j = tid;
        float acc[8];
#pragma unroll
        for (int r = 0; r < 8; r++) acc[r] = 0.0f;
#pragma unroll 4
        for (int k = 0; k < 128; k++) {
            float w = W2[k * 64 + j];
#pragma unroll
            for (int r = 0; r < 8; r++) acc[r] = fmaf(hs[r][k], w, acc[r]);
        }
        const float G = g2[j] * RSQ, B = be2[j], bb = b2[j];
#pragma unroll
        for (int r = 0; r < 8; r++)
            h2s[r][j] = fmaxf(fmaf(G, acc[r] + bb, B), 0.0f);
    }
    __syncthreads();

    if (tid < 8) {
        const int r = tid;
        float s = b3[0];
#pragma unroll 8
        for (int k = 0; k < 64; k++) s = fmaf(h2s[r][k], W3[k], s);
        float a = 1.0f / (1.0f + __expf(-s));
        atomicAdd(&g_agg_sum, a);
    }
}

// ---------------------------------------------------------------------------
// bf16 mma.sync gram, cp.async double-buffered, + fused sim epilogue.
// One CTA = one 128x128 tile (bi<=bj). 256 threads = 8 warps (2x4),
// warp tile 64x32. K in 32 chunks of 32 bf16 (64 B rows, SW64 swizzle),
// 2-stage cp.async pipeline. __launch_bounds__(256,2) -> 2 CTAs/SM.
// ---------------------------------------------------------------------------
#define GK2    32                  // bf16 K per chunk (=64 bytes per row)
#define NCH2   (DD / GK2)          // 32 chunks
#define STAGE_BYTES (128 * 64)     // 8 KB per operand per stage

__global__ __launch_bounds__(256, 2) void gram_sim_kernel() {
    __shared__ __align__(1024) unsigned char s_A[2 * STAGE_BYTES];
    __shared__ __align__(1024) unsigned char s_B[2 * STAGE_BYTES];
    __shared__ float s_sqi[128], s_rni[128], s_sqj[128], s_rnj[128];
    __shared__ float s_warpsum[8];

    // tile id -> (bi, bj), bi <= bj, t = bj*(bj+1)/2 + bi
    const int t = blockIdx.x;
    int bj = (int)((sqrtf(8.0f * (float)t + 1.0f) - 1.0f) * 0.5f);
    while ((bj + 1) * (bj + 2) / 2 <= t) bj++;
    while (bj * (bj + 1) / 2 > t) bj--;
    const int bi = t - bj * (bj + 1) / 2;
    const int rowA0 = bi * 128, rowB0 = bj * 128;

    const int tid  = threadIdx.x;
    const int wid  = tid >> 5;
    const int lane = tid & 31;
    const int m0 = (wid >> 2) * 64;   // warp row offset (0 or 64)
    const int n0 = (wid & 3) * 32;    // warp col offset (0,32,64,96)

    // stage stats
    if (tid < 128) {
        s_sqi[tid] = g_sq[rowA0 + tid];
        s_rni[tid] = g_rnorm[rowA0 + tid];
    } else {
        int j = tid - 128;
        s_sqj[j] = g_sq[rowB0 + j];
        s_rnj[j] = g_rnorm[rowB0 + j];
    }

    const uint32_t sA = smem_to_u32(s_A);
    const uint32_t sB = smem_to_u32(s_B);
    const __nv_bfloat16* __restrict__ Fb = g_Fbf;

    // per-thread cooperative-load slots: 2 segs (16B) per operand per chunk
    const int ld_row0 = tid >> 2;              // rows 0..63   (it=0)
    const int ld_row1 = (tid + 256) >> 2;      // rows 64..127 (it=1)
    const int ld_seg  = tid & 3;
    const uint32_t ld_off0 = swz64((uint32_t)(ld_row0 * 64 + ld_seg * 16));
    const uint32_t ld_off1 = swz64((uint32_t)(ld_row1 * 64 + ld_seg * 16));
    const __nv_bfloat16* gA0 = Fb + (size_t)(rowA0 + ld_row0) * DD + ld_seg * 8;
    const __nv_bfloat16* gA1 = Fb + (size_t)(rowA0 + ld_row1) * DD + ld_seg * 8;
    const __nv_bfloat16* gB0 = Fb + (size_t)(rowB0 + ld_row0) * DD + ld_seg * 8;
    const __nv_bfloat16* gB1 = Fb + (size_t)(rowB0 + ld_row1) * DD + ld_seg * 8;

    float acc[4][4][4];
#pragma unroll
    for (int mi = 0; mi < 4; mi++)
#pragma unroll
        for (int ni = 0; ni < 4; ni++)
#pragma unroll
            for (int r = 0; r < 4; r++) acc[mi][ni][r] = 0.0f;

    // ldmatrix smem addresses (swizzled); ks-advance is XOR 0x20
    uint32_t a_addr[4], b_addr[4];
#pragma unroll
    for (int mi = 0; mi < 4; mi++) {
        uint32_t row = m0 + mi * 16 + (lane & 15);
        a_addr[mi] = sA + swz64(row * 64 + (lane >> 4) * 16);
    }
#pragma unroll
    for (int ni = 0; ni < 4; ni++) {
        uint32_t row = n0 + ni * 8 + (lane & 7);
        b_addr[ni] = sB + swz64(row * 64 + ((lane >> 3) & 1) * 16);
    }

    // ---- 2-stage cp.async pipeline over 32 chunks ----
    // prefetch chunk 0 into stage 0
    {
        CP_ASYNC16(sA + ld_off0, gA0);
        CP_ASYNC16(sA + ld_off1, gA1);
        CP_ASYNC16(sB + ld_off0, gB0);
        CP_ASYNC16(sB + ld_off1, gB1);
        CP_COMMIT();
    }

    for (int kt = 0; kt < NCH2; kt++) {
        if (kt + 1 < NCH2) {
            const uint32_t sb = ((kt + 1) & 1) * STAGE_BYTES;
            const int kb = (kt + 1) * GK2;
            CP_ASYNC16(sA + sb + ld_off0, gA0 + kb);
            CP_ASYNC16(sA + sb + ld_off1, gA1 + kb);
            CP_ASYNC16(sB + sb + ld_off0, gB0 + kb);
            CP_ASYNC16(sB + sb + ld_off1, gB1 + kb);
            CP_COMMIT();
            CP_WAIT(1);
        } else {
            CP_WAIT(0);
        }
        __syncthreads();

        const uint32_t st = (kt & 1) * STAGE_BYTES;
#pragma unroll
        for (int ks = 0; ks < 2; ks++) {
            const uint32_t kb = ks * 32;   // 16 bf16 = 32 B, XOR-advance
            uint32_t af[4][4];
#pragma unroll
            for (int mi = 0; mi < 4; mi++)
                ldsm_x4(af[mi][0], af[mi][1], af[mi][2], af[mi][3],
                        (a_addr[mi] + st) ^ kb);
            uint32_t bf[4][2];
#pragma unroll
            for (int ni = 0; ni < 4; ni++)
                ldsm_x2(bf[ni][0], bf[ni][1], (b_addr[ni] + st) ^ kb);
#pragma unroll
            for (int mi = 0; mi < 4; mi++)
#pragma unroll
                for (int ni = 0; ni < 4; ni++)
                    mma_bf16(acc[mi][ni], af[mi], bf[ni]);
        }
        __syncthreads();
    }

    // --- fused similarity epilogue on register accumulators ---
    // m16n8 D mapping: rows = lane>>2 (+8), cols = 2*(lane&3) (+1)
    const int grp = lane >> 2, tg = lane & 3;
    const bool diag_tile = (bi == bj);

    float lsum = 0.0f;
#pragma unroll
    for (int mi = 0; mi < 4; mi++) {
        const int r0r = m0 + mi * 16 + grp;
        const int r1r = r0r + 8;
        const float sq_r[2] = { s_sqi[r0r], s_sqi[r1r] };
        const float rn_r[2] = { s_rni[r0r], s_rni[r1r] };
#pragma unroll
        for (int ni = 0; ni < 4; ni++) {
            const int c0 = n0 + ni * 8 + tg * 2;
#pragma unroll
            for (int rr = 0; rr < 2; rr++) {
#pragma unroll
                for (int cc = 0; cc < 2; cc++) {
                    const int rowl = rr ? r1r : r0r;
                    const int coll = c0 + cc;
                    const float g = acc[mi][ni][rr * 2 + cc];
                    const float cosv = g * rn_r[rr] * s_rnj[coll];
                    const float d2 = fmaxf(sq_r[rr] + s_sqj[coll] - 2.0f * g, 0.0f);
                    const float den = fmaxf(1024.0f * (1.0f + cosv), 1e-6f);
                    float s = __expf(-__fdividef(d2, den));
                    if (diag_tile && rowl == coll) s = 1.0f;
                    lsum += s;
                }
            }
        }
    }

    // block reduce + accumulate
#pragma unroll
    for (int o = 16; o > 0; o >>= 1) lsum += __shfl_down_sync(0xffffffffu, lsum, o);
    if (lane == 0) s_warpsum[wid] = lsum;
    __syncthreads();
    if (tid == 0) {
        float tot = 0.0f;
#pragma unroll
        for (int w = 0; w < 8; w++) tot += s_warpsum[w];
        const double wgt = diag_tile ? 1.0 : 2.0;
        atomicAdd(&g_sim_sum, wgt * (double)tot);
    }
}

// ---------------------------------------------------------------------------
__global__ void finalize_kernel(float* __restrict__ out) {
    const double ma = (double)g_agg_sum / (double)NN;
    const double ms = g_sim_sum / ((double)NN * (double)NN);
    out[0] = (float)(ma * ms);
}

// ---------------------------------------------------------------------------
extern "C" void kernel_launch(void* const* d_in, const int* in_sizes, int n_in,
                              void* d_out, int out_size)
{
    const float* F      = (const float*)d_in[0];   // [9216, 1024]
    const float* scores = (const float*)d_in[1];   // [9216]
    const float* W1     = (const float*)d_in[2];   // [1025, 128]
    const float* b1     = (const float*)d_in[3];
    const float* g1     = (const float*)d_in[4];
    const float* be1    = (const float*)d_in[5];
    const float* W2     = (const float*)d_in[6];   // [128, 64]
    const float* b2     = (const float*)d_in[7];
    const float* g2     = (const float*)d_in[8];
    const float* be2    = (const float*)d_in[9];
    const float* W3     = (const float*)d_in[10];  // [64, 1]
    const float* b3     = (const float*)d_in[11];

    init_kernel<<<1, 1>>>();
    prep_kernel<<<NN / 8, dim3(32, 8)>>>(F);
    mlp_kernel<<<NN / 8, 128>>>(F, scores, W1, b1, g1, be1, W2, b2, g2, be2, W3, b3);
    gram_sim_kernel<<<NTILES, 256>>>();
    finalize_kernel<<<1, 1>>>((float*)d_out);
}

// round 15
// speedup vs baseline: 1.4147x; 1.4147x over previous
#include <cuda_runtime.h>
#include <cuda_bf16.h>
#include <math.h>
#include <stdint.h>

#define NN 9216
#define DD 1024
#define NB 72          // NN / 128 tile blocks per dim
#define NTILES 2628    // NB*(NB+1)/2 upper-triangular tiles
#define MLPB 72        // MLP row-blocks (128 rows each)

// -------- device-global accumulators / scratch (no allocations allowed) -----
__device__ float  g_sq[NN];
__device__ float  g_rnorm[NN];
__device__ float  g_agg_sum;
__device__ double g_sim_sum;
__device__ __align__(16) __nv_bfloat16 g_Fbf[(size_t)NN * DD];
__device__ __align__(16) __nv_bfloat16 g_W1T[128 * 1024];   // W1 transposed, bf16

// ---------------------------------------------------------------------------
__device__ __forceinline__ uint32_t smem_to_u32(const void* p) {
    uint32_t a;
    asm("{ .reg .u64 t; cvta.to.shared.u64 t, %1; cvt.u32.u64 %0, t; }"
        : "=r"(a) : "l"(p));
    return a;
}

__device__ __forceinline__ void ldsm_x4(uint32_t& r0, uint32_t& r1,
                                        uint32_t& r2, uint32_t& r3, uint32_t addr) {
    asm volatile("ldmatrix.sync.aligned.m8n8.x4.shared.b16 {%0,%1,%2,%3}, [%4];"
                 : "=r"(r0), "=r"(r1), "=r"(r2), "=r"(r3) : "r"(addr));
}

__device__ __forceinline__ void ldsm_x2(uint32_t& r0, uint32_t& r1, uint32_t addr) {
    asm volatile("ldmatrix.sync.aligned.m8n8.x2.shared.b16 {%0,%1}, [%2];"
                 : "=r"(r0), "=r"(r1) : "r"(addr));
}

__device__ __forceinline__ void mma_bf16(float d[4], const uint32_t a[4],
                                         const uint32_t b[2]) {
    asm volatile(
        "mma.sync.aligned.m16n8k16.row.col.f32.bf16.bf16.f32 "
        "{%0,%1,%2,%3}, {%4,%5,%6,%7}, {%8,%9}, {%0,%1,%2,%3};"
        : "+f"(d[0]), "+f"(d[1]), "+f"(d[2]), "+f"(d[3])
        : "r"(a[0]), "r"(a[1]), "r"(a[2]), "r"(a[3]), "r"(b[0]), "r"(b[1]));
}

#define CP_ASYNC16(dst_u32, src_ptr) \
    asm volatile("cp.async.cg.shared.global [%0], [%1], 16;" \
                 :: "r"(dst_u32), "l"(src_ptr))
#define CP_COMMIT() asm volatile("cp.async.commit_group;" ::: "memory")
#define CP_WAIT(n)  asm volatile("cp.async.wait_group %0;" :: "n"(n) : "memory")

// swizzles: XOR of 16B-seg bits with row bits; both commute with in-row
// k-step XOR advances (kb never touches the source-bit fields).
__device__ __forceinline__ uint32_t swz64(uint32_t off) {   // 64 B rows
    return off ^ ((off >> 3) & 0x30);
}
__device__ __forceinline__ uint32_t swz128(uint32_t off) {  // 128 B rows
    return off ^ ((off >> 3) & 0x70);
}

// ---------------------------------------------------------------------------
__global__ void init_kernel() {
    g_agg_sum = 0.0f;
    g_sim_sum = 0.0;
}

// one warp per row: squared norm, reciprocal norm, and bf16 conversion
__global__ void prep_kernel(const float* __restrict__ F) {
    int row = blockIdx.x * blockDim.y + threadIdx.y;
    if (row >= NN) return;
    int lane = threadIdx.x;
    const float4* Fr = reinterpret_cast<const float4*>(F + (size_t)row * DD);
    uint2* out = reinterpret_cast<uint2*>(g_Fbf + (size_t)row * DD);
    float s = 0.0f;
#pragma unroll
    for (int w = 0; w < 8; w++) {
        float4 v = Fr[lane + w * 32];
        s += v.x * v.x + v.y * v.y + v.z * v.z + v.w * v.w;
        __nv_bfloat162 lo = __floats2bfloat162_rn(v.x, v.y);
        __nv_bfloat162 hi = __floats2bfloat162_rn(v.z, v.w);
        uint2 u;
        u.x = *reinterpret_cast<uint32_t*>(&lo);
        u.y = *reinterpret_cast<uint32_t*>(&hi);
        out[lane + w * 32] = u;
    }
#pragma unroll
    for (int o = 16; o > 0; o >>= 1) s += __shfl_down_sync(0xffffffffu, s, o);
    if (lane == 0) {
        g_sq[row] = s;
        g_rnorm[row] = rsqrtf(s);
    }
}

// W1 [1025,128] -> g_W1T [128,1024] bf16 (last row handled fp32 separately)
__global__ void w1t_kernel(const float* __restrict__ W1) {
    const int j = blockIdx.x;               // 0..127 output feature
    for (int k = threadIdx.x; k < 1024; k += 256)
        g_W1T[j * 1024 + k] = __float2bfloat16(W1[k * 128 + j]);
}

// ---------------------------------------------------------------------------
// Fused kernel. blocks [0,72): MLP 128-row tile via bf16 mma; blocks [72, 72+
// 2628): gram 128x128 tile, 3-stage cp.async pipeline + fused sim epilogue.
// 256 threads = 8 warps (2x4), warp tile 64x32 (4x4 m16n8k16).
// ---------------------------------------------------------------------------
#define GK2    32                  // gram: bf16 K per chunk (64 B rows)
#define NCH2   (DD / GK2)          // 32 chunks
#define STG    16384               // gram: per-stage bytes (A 8K + B 8K)

__global__ __launch_bounds__(256, 2) void fused_kernel(
    const float* __restrict__ scores,
    const float* __restrict__ W1, const float* __restrict__ b1,
    const float* __restrict__ g1, const float* __restrict__ be1,
    const float* __restrict__ W2, const float* __restrict__ b2,
    const float* __restrict__ g2, const float* __restrict__ be2,
    const float* __restrict__ W3, const float* __restrict__ b3)
{
    __shared__ __align__(1024) unsigned char s_raw[49152];

    const int tid  = threadIdx.x;
    const int wid  = tid >> 5;
    const int lane = tid & 31;
    const int m0 = (wid >> 2) * 64;
    const int n0 = (wid & 3) * 32;
    const int grp = lane >> 2, tg = lane & 3;
    const uint32_t sR = smem_to_u32(s_raw);

    if (blockIdx.x < MLPB) {
        // ==================== MLP path ====================
        const int rowA0 = blockIdx.x * 128;
        const __nv_bfloat16* __restrict__ Fb = g_Fbf;
        const __nv_bfloat16* __restrict__ Wt = g_W1T;

        float acc[4][4][4];
#pragma unroll
        for (int mi = 0; mi < 4; mi++)
#pragma unroll
            for (int ni = 0; ni < 4; ni++)
#pragma unroll
                for (int r = 0; r < 4; r++) acc[mi][ni][r] = 0.0f;

        uint32_t a_addr[4], b_addr[4];
#pragma unroll
        for (int mi = 0; mi < 4; mi++) {
            uint32_t row = m0 + mi * 16 + (lane & 15);
            a_addr[mi] = sR + swz128(row * 128 + (lane >> 4) * 16);
        }
#pragma unroll
        for (int ni = 0; ni < 4; ni++) {
            uint32_t row = n0 + ni * 8 + (lane & 7);
            b_addr[ni] = sR + 16384 + swz128(row * 128 + ((lane >> 3) & 1) * 16);
        }

        for (int kt = 0; kt < 16; kt++) {
            const int kbase = kt * 64;
#pragma unroll
            for (int it = 0; it < 4; it++) {
                int sidx = tid + it * 256;
                int row = sidx >> 3, seg = sidx & 7;
                uint32_t off = swz128((uint32_t)(row * 128 + seg * 16));
                *reinterpret_cast<uint4*>(s_raw + off) =
                    *reinterpret_cast<const uint4*>(
                        Fb + (size_t)(rowA0 + row) * DD + kbase + seg * 8);
                *reinterpret_cast<uint4*>(s_raw + 16384 + off) =
                    *reinterpret_cast<const uint4*>(
                        Wt + (size_t)row * 1024 + kbase + seg * 8);
            }
            __syncthreads();
#pragma unroll
            for (int ks = 0; ks < 4; ks++) {
                const uint32_t kb = ks * 32;
                uint32_t af[4][4];
#pragma unroll
                for (int mi = 0; mi < 4; mi++)
                    ldsm_x4(af[mi][0], af[mi][1], af[mi][2], af[mi][3],
                            a_addr[mi] ^ kb);
                uint32_t bf[4][2];
#pragma unroll
                for (int ni = 0; ni < 4; ni++)
                    ldsm_x2(bf[ni][0], bf[ni][1], b_addr[ni] ^ kb);
#pragma unroll
                for (int mi = 0; mi < 4; mi++)
#pragma unroll
                    for (int ni = 0; ni < 4; ni++)
                        mma_bf16(acc[mi][ni], af[mi], bf[ni]);
            }
            __syncthreads();
        }

        // --- layer-1 epilogue: +b1 +score*W1_last, BN, relu -> h1 bf16 smem ---
        const float RSQ = rsqrtf(1.0f + 1e-5f);
        __nv_bfloat16* s_h1 = reinterpret_cast<__nv_bfloat16*>(s_raw); // stride 132
        float scr[4][2];
#pragma unroll
        for (int mi = 0; mi < 4; mi++) {
            scr[mi][0] = __ldg(scores + rowA0 + m0 + mi * 16 + grp);
            scr[mi][1] = __ldg(scores + rowA0 + m0 + mi * 16 + grp + 8);
        }
#pragma unroll
        for (int ni = 0; ni < 4; ni++) {
            const int c0 = n0 + ni * 8 + tg * 2;
            const float w1l0 = __ldg(W1 + 1024 * 128 + c0);
            const float w1l1 = __ldg(W1 + 1024 * 128 + c0 + 1);
            const float bb0 = __ldg(b1 + c0),      bb1 = __ldg(b1 + c0 + 1);
            const float G0  = __ldg(g1 + c0) * RSQ, G1 = __ldg(g1 + c0 + 1) * RSQ;
            const float Be0 = __ldg(be1 + c0),     Be1 = __ldg(be1 + c0 + 1);
#pragma unroll
            for (int mi = 0; mi < 4; mi++) {
#pragma unroll
                for (int rr = 0; rr < 2; rr++) {
                    const int rowl = m0 + mi * 16 + grp + rr * 8;
                    float v0 = fmaxf(fmaf(G0,
                        acc[mi][ni][rr * 2 + 0] + bb0 + scr[mi][rr] * w1l0, Be0), 0.0f);
                    float v1 = fmaxf(fmaf(G1,
                        acc[mi][ni][rr * 2 + 1] + bb1 + scr[mi][rr] * w1l1, Be1), 0.0f);
                    *reinterpret_cast<__nv_bfloat162*>(s_h1 + rowl * 132 + c0) =
                        __floats2bfloat162_rn(v0, v1);
                }
            }
        }
        __syncthreads();

        // --- layer 2 (fp32, h1 broadcast from smem) ---
        const int jj = (wid & 1) * 32 + lane;      // output col 0..63
        const int rbase = (wid >> 1) * 32;         // 32 rows per warp-pair
        float acc2[32];
#pragma unroll
        for (int r = 0; r < 32; r++) acc2[r] = 0.0f;
        for (int k = 0; k < 128; k++) {
            const float w2v = __ldg(W2 + k * 64 + jj);
#pragma unroll
            for (int r = 0; r < 32; r++)
                acc2[r] = fmaf(__bfloat162float(s_h1[(rbase + r) * 132 + k]),
                               w2v, acc2[r]);
        }
        // --- bn2 + relu + layer 3 partials, reduce across lanes ---
        const float G2 = __ldg(g2 + jj) * RSQ, Be2 = __ldg(be2 + jj);
        const float bb2 = __ldg(b2 + jj), w3v = __ldg(W3 + jj);
#pragma unroll
        for (int r = 0; r < 32; r++) {
            float h = fmaxf(fmaf(G2, acc2[r] + bb2, Be2), 0.0f);
            float p = h * w3v;
#pragma unroll
            for (int o = 16; o > 0; o >>= 1) p += __shfl_xor_sync(0xffffffffu, p, o);
            acc2[r] = p;
        }
        float* s_row = reinterpret_cast<float*>(s_raw + 34304);
        __syncthreads();
        if ((wid & 1) == 0 && lane == 0)
            for (int r = 0; r < 32; r++) s_row[rbase + r] = acc2[r];
        __syncthreads();
        if ((wid & 1) == 1 && lane == 0)
            for (int r = 0; r < 32; r++) s_row[rbase + r] += acc2[r];
        __syncthreads();

        float a = 0.0f;
        if (tid < 128) {
            float s = s_row[tid] + __ldg(b3);
            a = 1.0f / (1.0f + __expf(-s));
        }
#pragma unroll
        for (int o = 16; o > 0; o >>= 1) a += __shfl_xor_sync(0xffffffffu, a, o);
        float* s_red = reinterpret_cast<float*>(s_raw + 34816);
        if (lane == 0) s_red[wid] = a;
        __syncthreads();
        if (tid == 0) {
            float tot = 0.0f;
#pragma unroll
            for (int w = 0; w < 8; w++) tot += s_red[w];
            atomicAdd(&g_agg_sum, tot);
        }
        return;
    }

    // ==================== gram path (3-stage pipeline) ====================
    const int t = blockIdx.x - MLPB;
    int bj = (int)((sqrtf(8.0f * (float)t + 1.0f) - 1.0f) * 0.5f);
    while ((bj + 1) * (bj + 2) / 2 <= t) bj++;
    while (bj * (bj + 1) / 2 > t) bj--;
    const int bi = t - bj * (bj + 1) / 2;
    const int rowA0 = bi * 128, rowB0 = bj * 128;
    const __nv_bfloat16* __restrict__ Fb = g_Fbf;

    // per-thread cooperative-load slots (2 segs per operand per chunk)
    const int ld_row0 = tid >> 2;
    const int ld_row1 = (tid + 256) >> 2;
    const int ld_seg  = tid & 3;
    const uint32_t ld_off0 = swz64((uint32_t)(ld_row0 * 64 + ld_seg * 16));
    const uint32_t ld_off1 = swz64((uint32_t)(ld_row1 * 64 + ld_seg * 16));
    const __nv_bfloat16* gA0 = Fb + (size_t)(rowA0 + ld_row0) * DD + ld_seg * 8;
    const __nv_bfloat16* gA1 = Fb + (size_t)(rowA0 + ld_row1) * DD + ld_seg * 8;
    const __nv_bfloat16* gB0 = Fb + (size_t)(rowB0 + ld_row0) * DD + ld_seg * 8;
    const __nv_bfloat16* gB1 = Fb + (size_t)(rowB0 + ld_row1) * DD + ld_seg * 8;

    float acc[4][4][4];
#pragma unroll
    for (int mi = 0; mi < 4; mi++)
#pragma unroll
        for (int ni = 0; ni < 4; ni++)
#pragma unroll
            for (int r = 0; r < 4; r++) acc[mi][ni][r] = 0.0f;

    uint32_t a_addr[4], b_addr[4];
#pragma unroll
    for (int mi = 0; mi < 4; mi++) {
        uint32_t row = m0 + mi * 16 + (lane & 15);
        a_addr[mi] = sR + swz64(row * 64 + (lane >> 4) * 16);
    }
#pragma unroll
    for (int ni = 0; ni < 4; ni++) {
        uint32_t row = n0 + ni * 8 + (lane & 7);
        b_addr[ni] = sR + 8192 + swz64(row * 64 + ((lane >> 3) & 1) * 16);
    }

    // prologue: prefetch chunks 0,1 into stages 0,1
#pragma unroll
    for (int c = 0; c < 2; c++) {
        const uint32_t base = sR + c * STG;
        const int kb = c * GK2;
        CP_ASYNC16(base + ld_off0, gA0 + kb);
        CP_ASYNC16(base + ld_off1, gA1 + kb);
        CP_ASYNC16(base + 8192 + ld_off0, gB0 + kb);
        CP_ASYNC16(base + 8192 + ld_off1, gB1 + kb);
        CP_COMMIT();
    }

    int stage = 0;   // kt % 3
    for (int kt = 0; kt < NCH2; kt++) {
        if (kt == NCH2 - 1) { CP_WAIT(0); } else { CP_WAIT(1); }
        __syncthreads();

        const uint32_t st = (uint32_t)stage * STG;
#pragma unroll
        for (int ks = 0; ks < 2; ks++) {
            const uint32_t kb = ks * 32;
            uint32_t af[4][4];
#pragma unroll
            for (int mi = 0; mi < 4; mi++)
                ldsm_x4(af[mi][0], af[mi][1], af[mi][2], af[mi][3],
                        (a_addr[mi] + st) ^ kb);
            uint32_t bf[4][2];
#pragma unroll
            for (int ni = 0; ni < 4; ni++)
                ldsm_x2(bf[ni][0], bf[ni][1], (b_addr[ni] + st) ^ kb);
#pragma unroll
            for (int mi = 0; mi < 4; mi++)
#pragma unroll
                for (int ni = 0; ni < 4; ni++)
                    mma_bf16(acc[mi][ni], af[mi], bf[ni]);
        }

        if (kt + 2 < NCH2) {
            int ns = stage + 2; if (ns >= 3) ns -= 3;   // (kt+2) % 3
            const uint32_t base = sR + (uint32_t)ns * STG;
            const int kb = (kt + 2) * GK2;
            CP_ASYNC16(base + ld_off0, gA0 + kb);
            CP_ASYNC16(base + ld_off1, gA1 + kb);
            CP_ASYNC16(base + 8192 + ld_off0, gB0 + kb);
            CP_ASYNC16(base + 8192 + ld_off1, gB1 + kb);
            CP_COMMIT();
        }
        if (++stage == 3) stage = 0;
    }

    // --- stats overlay (stage-0 bytes; all warps past kt=31 barrier, stage 0
    // last read at kt=30, so writes are race-free) ---
    float* s_stat = reinterpret_cast<float*>(s_raw);
    if (tid < 128) {
        s_stat[tid]       = g_sq[rowA0 + tid];
        s_stat[128 + tid] = g_rnorm[rowA0 + tid];
    } else {
        const int j = tid - 128;
        s_stat[256 + j] = g_sq[rowB0 + j];
        s_stat[384 + j] = g_rnorm[rowB0 + j];
    }
    __syncthreads();

    const bool diag_tile = (bi == bj);
    float lsum = 0.0f;
#pragma unroll
    for (int mi = 0; mi < 4; mi++) {
        const int r0r = m0 + mi * 16 + grp;
        const int r1r = r0r + 8;
        const float sq_r[2] = { s_stat[r0r], s_stat[r1r] };
        const float rn_r[2] = { s_stat[128 + r0r], s_stat[128 + r1r] };
#pragma unroll
        for (int ni = 0; ni < 4; ni++) {
            const int c0 = n0 + ni * 8 + tg * 2;
#pragma unroll
            for (int rr = 0; rr < 2; rr++) {
#pragma unroll
                for (int cc = 0; cc < 2; cc++) {
                    const int rowl = rr ? r1r : r0r;
                    const int coll = c0 + cc;
                    const float g = acc[mi][ni][rr * 2 + cc];
                    const float cosv = g * rn_r[rr] * s_stat[384 + coll];
                    const float d2 = fmaxf(sq_r[rr] + s_stat[256 + coll] - 2.0f * g, 0.0f);
                    const float den = fmaxf(1024.0f * (1.0f + cosv), 1e-6f);
                    float s = __expf(-__fdividef(d2, den));
                    if (diag_tile && rowl == coll) s = 1.0f;
                    lsum += s;
                }
            }
        }
    }

#pragma unroll
    for (int o = 16; o > 0; o >>= 1) lsum += __shfl_down_sync(0xffffffffu, lsum, o);
    if (lane == 0) s_stat[512 + wid] = lsum;
    __syncthreads();
    if (tid == 0) {
        float tot = 0.0f;
#pragma unroll
        for (int w = 0; w < 8; w++) tot += s_stat[512 + w];
        const double wgt = diag_tile ? 1.0 : 2.0;
        atomicAdd(&g_sim_sum, wgt * (double)tot);
    }
}

// ---------------------------------------------------------------------------
__global__ void finalize_kernel(float* __restrict__ out) {
    const double ma = (double)g_agg_sum / (double)NN;
    const double ms = g_sim_sum / ((double)NN * (double)NN);
    out[0] = (float)(ma * ms);
}

// ---------------------------------------------------------------------------
extern "C" void kernel_launch(void* const* d_in, const int* in_sizes, int n_in,
                              void* d_out, int out_size)
{
    const float* F      = (const float*)d_in[0];   // [9216, 1024]
    const float* scores = (const float*)d_in[1];   // [9216]
    const float* W1     = (const float*)d_in[2];   // [1025, 128]
    const float* b1     = (const float*)d_in[3];
    const float* g1     = (const float*)d_in[4];
    const float* be1    = (const float*)d_in[5];
    const float* W2     = (const float*)d_in[6];   // [128, 64]
    const float* b2     = (const float*)d_in[7];
    const float* g2     = (const float*)d_in[8];
    const float* be2    = (const float*)d_in[9];
    const float* W3     = (const float*)d_in[10];  // [64, 1]
    const float* b3     = (const float*)d_in[11];

    init_kernel<<<1, 1>>>();
    prep_kernel<<<NN / 8, dim3(32, 8)>>>(F);
    w1t_kernel<<<128, 256>>>(W1);
    fused_kernel<<<MLPB + NTILES, 256>>>(scores, W1, b1, g1, be1,
                                         W2, b2, g2, be2, W3, b3);
    finalize_kernel<<<1, 1>>>((float*)d_out);
}